// round 9
// baseline (speedup 1.0000x reference)
#include <cuda_runtime.h>
#include <cuda_fp16.h>
#include <cuda_bf16.h>
#include <mma.h>
#include <cstdint>

using namespace nvcuda;

#define N_NODES   100000
#define N_EDGES   1600000
#define IN_FEATS  64
#define OUT_FEATS 64
#define DIM       3
#define N_KERNELS 4
#define KH        (N_KERNELS * OUT_FEATS)   // 256

// ---- scratch (allocation-free rule) ----
__device__ __half g_h[(size_t)N_NODES * KH];   // node projections fp16 (51 MB)
__device__ __half g_W16[KH * IN_FEATS];        // W_fc in fp16 (32 KB)

// ---------------------------------------------------------------------------
// Kernel 0: convert W_fc to fp16 (one-time tiny kernel)
// ---------------------------------------------------------------------------
__global__ void wconv_kernel(const float* __restrict__ W_fc) {
    int i = blockIdx.x * blockDim.x + threadIdx.x;       // half2 index
    if (i < KH * IN_FEATS / 2) {
        float2 v = reinterpret_cast<const float2*>(W_fc)[i];
        reinterpret_cast<__half2*>(g_W16)[i] = __floats2half2_rn(v.x, v.y);
    }
}

// ---------------------------------------------------------------------------
// Kernel 1: tensor-core projection + fused out = feat + bias.
// Block: 256 threads (8 warps), 64 nodes.
// W staged in smem once per block; all wmma fragment loads hit smem.
// ---------------------------------------------------------------------------
#define NT 64   // nodes per block

__global__ __launch_bounds__(256) void proj_mma_kernel(const float* __restrict__ feat,
                                                       const float* __restrict__ bias,
                                                       float* __restrict__ out) {
    __shared__ __half As[NT * IN_FEATS];     // 8 KB, row-major ld=64
    __shared__ __half Ws[KH * IN_FEATS];     // 32 KB, W row-major = B col-major ld=64
    __shared__ float  stage[8][256];         // 8 KB, per-warp 16x16 C staging

    const int tid  = threadIdx.x;
    const int warp = tid >> 5;
    const int lane = tid & 31;
    const int node0 = blockIdx.x * NT;

    // --- stage W into smem (32 KB, fully coalesced uint4) ---
    {
        const uint4* wsrc = reinterpret_cast<const uint4*>(g_W16);
        uint4* wdst = reinterpret_cast<uint4*>(Ws);
#pragma unroll
        for (int q = 0; q < 8; q++)                      // 2048 uint4 / 256 thr
            wdst[tid + q * 256] = wsrc[tid + q * 256];
    }

    // --- load feat tile (fp32), convert to fp16 smem, fused out = feat + bias ---
    const float4* fsrc = reinterpret_cast<const float4*>(feat + (size_t)node0 * IN_FEATS);
    float4*       odst = reinterpret_cast<float4*>(out + (size_t)node0 * IN_FEATS);
    const float4* bp   = reinterpret_cast<const float4*>(bias);
    const int lim4 = min(NT, N_NODES - node0) * (IN_FEATS / 4);   // valid float4 count
#pragma unroll
    for (int q = 0; q < 4; q++) {
        int i = tid + q * 256;               // float4 index in tile (0..1023)
        float4 v = (i < lim4) ? fsrc[i] : make_float4(0.f, 0.f, 0.f, 0.f);
        __half2* adst = reinterpret_cast<__half2*>(As + i * 4);
        adst[0] = __floats2half2_rn(v.x, v.y);
        adst[1] = __floats2half2_rn(v.z, v.w);
        if (i < lim4) {
            float4 b = __ldg(bp + (i & 15));
            v.x += b.x; v.y += b.y; v.z += b.z; v.w += b.w;
            odst[i] = v;                     // out = feat + bias
        }
    }
    __syncthreads();

    // --- wmma: each warp: 2 n-tiles x 4 m-tiles, K = 4 steps of 16 ---
#pragma unroll
    for (int t = 0; t < 2; t++) {
        const int ni = warp * 2 + t;

        wmma::fragment<wmma::matrix_b, 16, 16, 16, __half, wmma::col_major> b[4];
#pragma unroll
        for (int k = 0; k < 4; k++)
            wmma::load_matrix_sync(b[k], Ws + (ni * 16) * IN_FEATS + k * 16, IN_FEATS);

#pragma unroll
        for (int mi = 0; mi < 4; mi++) {
            wmma::fragment<wmma::matrix_a, 16, 16, 16, __half, wmma::row_major> a;
            wmma::fragment<wmma::accumulator, 16, 16, 16, float> c;
            wmma::fill_fragment(c, 0.f);
#pragma unroll
            for (int k = 0; k < 4; k++) {
                wmma::load_matrix_sync(a, As + (mi * 16) * IN_FEATS + k * 16, IN_FEATS);
                wmma::mma_sync(c, a, b[k], c);
            }
            wmma::store_matrix_sync(stage[warp], c, 16, wmma::mem_row_major);
            __syncwarp();
            // lane -> (row = lane>>1, half-row = lane&1): 8 floats -> 8 halves -> 16B store
            const int row  = lane >> 1;
            const int hsel = lane & 1;
            const int node = node0 + mi * 16 + row;
            if (node < N_NODES) {
                const float* sp = stage[warp] + row * 16 + hsel * 8;
                __half2 h4[4];
#pragma unroll
                for (int q = 0; q < 4; q++)
                    h4[q] = __floats2half2_rn(sp[2*q], sp[2*q+1]);
                *reinterpret_cast<uint4*>(g_h + (size_t)node * KH + ni * 16 + hsel * 8) =
                    *reinterpret_cast<uint4*>(h4);
            }
            __syncwarp();
        }
    }
}

// ---------------------------------------------------------------------------
// L2 residency via createpolicy + cache_hint.
// ---------------------------------------------------------------------------
__device__ __forceinline__ uint64_t make_policy_evict_last() {
    uint64_t p;
    asm("createpolicy.fractional.L2::evict_last.b64 %0, 1.0;" : "=l"(p));
    return p;
}
__device__ __forceinline__ uint64_t make_policy_evict_first() {
    uint64_t p;
    asm("createpolicy.fractional.L2::evict_first.b64 %0, 1.0;" : "=l"(p));
    return p;
}
__device__ __forceinline__ float4 ldg_hint_v4(const float4* p, uint64_t pol) {
    float4 v;
    asm volatile("ld.global.nc.L2::cache_hint.v4.f32 {%0, %1, %2, %3}, [%4], %5;"
                 : "=f"(v.x), "=f"(v.y), "=f"(v.z), "=f"(v.w) : "l"(p), "l"(pol));
    return v;
}
__device__ __forceinline__ float ldg_hint_f32(const float* p, uint64_t pol) {
    float v;
    asm volatile("ld.global.nc.L2::cache_hint.f32 %0, [%1], %2;"
                 : "=f"(v) : "l"(p), "l"(pol));
    return v;
}
__device__ __forceinline__ int ldg_hint_s32(const int* p, uint64_t pol) {
    int v;
    asm volatile("ld.global.nc.L2::cache_hint.b32 %0, [%1], %2;"
                 : "=r"(v) : "l"(p), "l"(pol));
    return v;
}

// ---------------------------------------------------------------------------
// Kernel 2: edge scatter (unchanged from R7/R8: 139 us).
// 8 threads per edge; thread handles 8 consecutive output channels.
// ---------------------------------------------------------------------------
__global__ __launch_bounds__(256) void edge_kernel(const float* __restrict__ pseudo,
                                                   const int*   __restrict__ src,
                                                   const int*   __restrict__ dst,
                                                   const float* __restrict__ mu,
                                                   const float* __restrict__ inv_sigma,
                                                   float* __restrict__ out) {
    const int gid = blockIdx.x * blockDim.x + threadIdx.x;
    const int e   = gid >> 3;                  // edge index
    if (e >= N_EDGES) return;

    const uint64_t pol_keep   = make_policy_evict_last();
    const uint64_t pol_stream = make_policy_evict_first();

    const int lane = threadIdx.x & 31;
    const int sub  = gid & 7;
    const int kid  = sub & 3;

    float px = ldg_hint_f32(pseudo + 3*e + 0, pol_stream);
    float py = ldg_hint_f32(pseudo + 3*e + 1, pol_stream);
    float pz = ldg_hint_f32(pseudo + 3*e + 2, pol_stream);

    float d0 = px - __ldg(mu + kid*3 + 0);
    float d1 = py - __ldg(mu + kid*3 + 1);
    float d2 = pz - __ldg(mu + kid*3 + 2);
    float s0 = __ldg(inv_sigma + kid*3 + 0);
    float s1 = __ldg(inv_sigma + kid*3 + 1);
    float s2 = __ldg(inv_sigma + kid*3 + 2);

    float acc = d0*d0*s0*s0 + d1*d1*s1*s1 + d2*d2*s2*s2;
    float gv  = __expf(-0.5f * acc);

    const unsigned FULL = 0xffffffffu;
    const int base = lane & 24;
    float g0 = __shfl_sync(FULL, gv, base + 0);
    float g1 = __shfl_sync(FULL, gv, base + 1);
    float g2 = __shfl_sync(FULL, gv, base + 2);
    float g3 = __shfl_sync(FULL, gv, base + 3);

    const int s = ldg_hint_s32(src + e, pol_stream);
    const int d = ldg_hint_s32(dst + e, pol_stream);

    const float4* hp = reinterpret_cast<const float4*>(g_h + (size_t)s * KH);
    float4 r0 = ldg_hint_v4(hp + 0*8 + sub, pol_keep);
    float4 r1 = ldg_hint_v4(hp + 1*8 + sub, pol_keep);
    float4 r2 = ldg_hint_v4(hp + 2*8 + sub, pol_keep);
    float4 r3 = ldg_hint_v4(hp + 3*8 + sub, pol_keep);

    const __half2* h0 = reinterpret_cast<const __half2*>(&r0);
    const __half2* h1 = reinterpret_cast<const __half2*>(&r1);
    const __half2* h2 = reinterpret_cast<const __half2*>(&r2);
    const __half2* h3 = reinterpret_cast<const __half2*>(&r3);

    float m[8];
#pragma unroll
    for (int q = 0; q < 4; q++) {
        float2 a = __half22float2(h0[q]);
        float2 b = __half22float2(h1[q]);
        float2 c = __half22float2(h2[q]);
        float2 dd = __half22float2(h3[q]);
        m[2*q+0] = g0*a.x + g1*b.x + g2*c.x + g3*dd.x;
        m[2*q+1] = g0*a.y + g1*b.y + g2*c.y + g3*dd.y;
    }

    float* op = out + (size_t)d * OUT_FEATS + sub * 8;
    asm volatile("red.global.add.v4.f32 [%0], {%1, %2, %3, %4};"
                 :: "l"(op), "f"(m[0]), "f"(m[1]), "f"(m[2]), "f"(m[3])
                 : "memory");
    asm volatile("red.global.add.v4.f32 [%0], {%1, %2, %3, %4};"
                 :: "l"(op + 4), "f"(m[4]), "f"(m[5]), "f"(m[6]), "f"(m[7])
                 : "memory");
}

// ---------------------------------------------------------------------------
// Launch
// ---------------------------------------------------------------------------
extern "C" void kernel_launch(void* const* d_in, const int* in_sizes, int n_in,
                              void* d_out, int out_size) {
    const float* feat      = (const float*)d_in[0];   // [N, 64]
    const float* pseudo    = (const float*)d_in[1];   // [E, 3]
    const int*   src       = (const int*)  d_in[2];   // [E]
    const int*   dst       = (const int*)  d_in[3];   // [E]
    const float* W_fc      = (const float*)d_in[4];   // [256, 64]
    const float* mu        = (const float*)d_in[5];   // [4, 3]
    const float* inv_sigma = (const float*)d_in[6];   // [4, 3]
    const float* bias      = (const float*)d_in[7];   // [64]
    float* out = (float*)d_out;                       // [N, 64]

    // 0) W -> fp16
    wconv_kernel<<<(KH * IN_FEATS / 2 + 255) / 256, 256>>>(W_fc);

    // 1) tensor-core projection + out = feat + bias
    proj_mma_kernel<<<(N_NODES + NT - 1) / NT, 256>>>(feat, bias, out);

    // 2) edge scatter with vector atomics
    {
        long long threads = (long long)N_EDGES * 8;
        int blocks = (int)((threads + 255) / 256);            // 50000
        edge_kernel<<<blocks, 256>>>(pseudo, src, dst, mu, inv_sigma, out);
    }
}

// round 10
// speedup vs baseline: 1.1288x; 1.1288x over previous
#include <cuda_runtime.h>
#include <cuda_fp16.h>
#include <cuda_bf16.h>
#include <mma.h>
#include <cstdint>

using namespace nvcuda;

#define N_NODES   100000
#define N_EDGES   1600000
#define IN_FEATS  64
#define OUT_FEATS 64
#define DIM       3
#define N_KERNELS 4
#define KH        (N_KERNELS * OUT_FEATS)   // 256

// ---- scratch (allocation-free rule) ----
__device__ __half g_h[(size_t)N_NODES * KH];   // node projections fp16 (51 MB)
__device__ __half g_W16[KH * IN_FEATS];        // W_fc in fp16 (32 KB, L1-resident)

// ---------------------------------------------------------------------------
// Kernel 0: convert W_fc to fp16
// ---------------------------------------------------------------------------
__global__ void wconv_kernel(const float* __restrict__ W_fc) {
    int i = blockIdx.x * blockDim.x + threadIdx.x;       // half2 index
    if (i < KH * IN_FEATS / 2) {
        float2 v = reinterpret_cast<const float2*>(W_fc)[i];
        reinterpret_cast<__half2*>(g_W16)[i] = __floats2half2_rn(v.x, v.y);
    }
}

// Empty kernels: shift ncu's captured launch (#3 overall) onto proj_mma_kernel.
__global__ void nop_kernel() {}

// ---------------------------------------------------------------------------
// Kernel 1: tensor-core projection + fused out = feat + bias.  (v3)
// Block: 256 threads (8 warps), NT=128 nodes (8 m-tiles).
// Warp w owns n-tiles {2w, 2w+1}; B fragments loaded ONCE per warp (global,
// L1-resident), A fragments loaded once per m-tile and reused for both n-tiles.
// ---------------------------------------------------------------------------
#define NT 128   // nodes per block

__global__ __launch_bounds__(256) void proj_mma_kernel(const float* __restrict__ feat,
                                                       const float* __restrict__ bias,
                                                       float* __restrict__ out) {
    __shared__ __half As[NT * IN_FEATS];     // 16 KB, row-major ld=64
    __shared__ float  stage[8][256];         // 8 KB, per-warp 16x16 C staging

    const int tid  = threadIdx.x;
    const int warp = tid >> 5;
    const int lane = tid & 31;
    const int node0 = blockIdx.x * NT;

    // --- load feat tile (fp32), convert to fp16 smem, fused out = feat + bias ---
    const float4* fsrc = reinterpret_cast<const float4*>(feat + (size_t)node0 * IN_FEATS);
    float4*       odst = reinterpret_cast<float4*>(out + (size_t)node0 * IN_FEATS);
    const float4* bp   = reinterpret_cast<const float4*>(bias);
    const int lim4 = (min(NT, N_NODES - node0)) * (IN_FEATS / 4);   // valid float4 count
#pragma unroll
    for (int q = 0; q < 8; q++) {
        int i = tid + q * 256;               // float4 index in tile (0..2047)
        float4 v = (i < lim4) ? fsrc[i] : make_float4(0.f, 0.f, 0.f, 0.f);
        __half2* adst = reinterpret_cast<__half2*>(As + i * 4);
        adst[0] = __floats2half2_rn(v.x, v.y);
        adst[1] = __floats2half2_rn(v.z, v.w);
        if (i < lim4) {
            float4 b = __ldg(bp + (i & 15));
            v.x += b.x; v.y += b.y; v.z += b.z; v.w += b.w;
            odst[i] = v;                     // out = feat + bias
        }
    }
    __syncthreads();

    // --- B fragments: 2 n-tiles x 4 k-steps, loaded once (L1-resident W) ---
    wmma::fragment<wmma::matrix_b, 16, 16, 16, __half, wmma::col_major> b[2][4];
#pragma unroll
    for (int t = 0; t < 2; t++) {
        const int ni = warp * 2 + t;
#pragma unroll
        for (int k = 0; k < 4; k++)
            wmma::load_matrix_sync(b[t][k], g_W16 + (ni * 16) * IN_FEATS + k * 16, IN_FEATS);
    }

    // --- loop m-tiles: load A once, mma into both n accumulators ---
#pragma unroll
    for (int mi = 0; mi < 8; mi++) {
        wmma::fragment<wmma::matrix_a, 16, 16, 16, __half, wmma::row_major> a[4];
#pragma unroll
        for (int k = 0; k < 4; k++)
            wmma::load_matrix_sync(a[k], As + (mi * 16) * IN_FEATS + k * 16, IN_FEATS);

#pragma unroll
        for (int t = 0; t < 2; t++) {
            const int ni = warp * 2 + t;
            wmma::fragment<wmma::accumulator, 16, 16, 16, float> c;
            wmma::fill_fragment(c, 0.f);
#pragma unroll
            for (int k = 0; k < 4; k++)
                wmma::mma_sync(c, a[k], b[t][k], c);

            wmma::store_matrix_sync(stage[warp], c, 16, wmma::mem_row_major);
            __syncwarp();
            // lane -> (row = lane>>1, half-row = lane&1): 8 floats -> 8 halves -> 16B store
            const int row  = lane >> 1;
            const int hsel = lane & 1;
            const int node = node0 + mi * 16 + row;
            if (node < N_NODES) {
                const float* sp = stage[warp] + row * 16 + hsel * 8;
                __half2 h4[4];
#pragma unroll
                for (int q = 0; q < 4; q++)
                    h4[q] = __floats2half2_rn(sp[2*q], sp[2*q+1]);
                *reinterpret_cast<uint4*>(g_h + (size_t)node * KH + ni * 16 + hsel * 8) =
                    *reinterpret_cast<uint4*>(h4);
            }
            __syncwarp();
        }
    }
}

// ---------------------------------------------------------------------------
// L2 residency via createpolicy + cache_hint.
// ---------------------------------------------------------------------------
__device__ __forceinline__ uint64_t make_policy_evict_last() {
    uint64_t p;
    asm("createpolicy.fractional.L2::evict_last.b64 %0, 1.0;" : "=l"(p));
    return p;
}
__device__ __forceinline__ uint64_t make_policy_evict_first() {
    uint64_t p;
    asm("createpolicy.fractional.L2::evict_first.b64 %0, 1.0;" : "=l"(p));
    return p;
}
__device__ __forceinline__ float4 ldg_hint_v4(const float4* p, uint64_t pol) {
    float4 v;
    asm volatile("ld.global.nc.L2::cache_hint.v4.f32 {%0, %1, %2, %3}, [%4], %5;"
                 : "=f"(v.x), "=f"(v.y), "=f"(v.z), "=f"(v.w) : "l"(p), "l"(pol));
    return v;
}
__device__ __forceinline__ float ldg_hint_f32(const float* p, uint64_t pol) {
    float v;
    asm volatile("ld.global.nc.L2::cache_hint.f32 %0, [%1], %2;"
                 : "=f"(v) : "l"(p), "l"(pol));
    return v;
}
__device__ __forceinline__ int ldg_hint_s32(const int* p, uint64_t pol) {
    int v;
    asm volatile("ld.global.nc.L2::cache_hint.b32 %0, [%1], %2;"
                 : "=r"(v) : "l"(p), "l"(pol));
    return v;
}

// ---------------------------------------------------------------------------
// Kernel 2: edge scatter (unchanged: 139 us, REDG-issue bound).
// ---------------------------------------------------------------------------
__global__ __launch_bounds__(256) void edge_kernel(const float* __restrict__ pseudo,
                                                   const int*   __restrict__ src,
                                                   const int*   __restrict__ dst,
                                                   const float* __restrict__ mu,
                                                   const float* __restrict__ inv_sigma,
                                                   float* __restrict__ out) {
    const int gid = blockIdx.x * blockDim.x + threadIdx.x;
    const int e   = gid >> 3;                  // edge index
    if (e >= N_EDGES) return;

    const uint64_t pol_keep   = make_policy_evict_last();
    const uint64_t pol_stream = make_policy_evict_first();

    const int lane = threadIdx.x & 31;
    const int sub  = gid & 7;
    const int kid  = sub & 3;

    float px = ldg_hint_f32(pseudo + 3*e + 0, pol_stream);
    float py = ldg_hint_f32(pseudo + 3*e + 1, pol_stream);
    float pz = ldg_hint_f32(pseudo + 3*e + 2, pol_stream);

    float d0 = px - __ldg(mu + kid*3 + 0);
    float d1 = py - __ldg(mu + kid*3 + 1);
    float d2 = pz - __ldg(mu + kid*3 + 2);
    float s0 = __ldg(inv_sigma + kid*3 + 0);
    float s1 = __ldg(inv_sigma + kid*3 + 1);
    float s2 = __ldg(inv_sigma + kid*3 + 2);

    float acc = d0*d0*s0*s0 + d1*d1*s1*s1 + d2*d2*s2*s2;
    float gv  = __expf(-0.5f * acc);

    const unsigned FULL = 0xffffffffu;
    const int base = lane & 24;
    float g0 = __shfl_sync(FULL, gv, base + 0);
    float g1 = __shfl_sync(FULL, gv, base + 1);
    float g2 = __shfl_sync(FULL, gv, base + 2);
    float g3 = __shfl_sync(FULL, gv, base + 3);

    const int s = ldg_hint_s32(src + e, pol_stream);
    const int d = ldg_hint_s32(dst + e, pol_stream);

    const float4* hp = reinterpret_cast<const float4*>(g_h + (size_t)s * KH);
    float4 r0 = ldg_hint_v4(hp + 0*8 + sub, pol_keep);
    float4 r1 = ldg_hint_v4(hp + 1*8 + sub, pol_keep);
    float4 r2 = ldg_hint_v4(hp + 2*8 + sub, pol_keep);
    float4 r3 = ldg_hint_v4(hp + 3*8 + sub, pol_keep);

    const __half2* h0 = reinterpret_cast<const __half2*>(&r0);
    const __half2* h1 = reinterpret_cast<const __half2*>(&r1);
    const __half2* h2 = reinterpret_cast<const __half2*>(&r2);
    const __half2* h3 = reinterpret_cast<const __half2*>(&r3);

    float m[8];
#pragma unroll
    for (int q = 0; q < 4; q++) {
        float2 a = __half22float2(h0[q]);
        float2 b = __half22float2(h1[q]);
        float2 c = __half22float2(h2[q]);
        float2 dd = __half22float2(h3[q]);
        m[2*q+0] = g0*a.x + g1*b.x + g2*c.x + g3*dd.x;
        m[2*q+1] = g0*a.y + g1*b.y + g2*c.y + g3*dd.y;
    }

    float* op = out + (size_t)d * OUT_FEATS + sub * 8;
    asm volatile("red.global.add.v4.f32 [%0], {%1, %2, %3, %4};"
                 :: "l"(op), "f"(m[0]), "f"(m[1]), "f"(m[2]), "f"(m[3])
                 : "memory");
    asm volatile("red.global.add.v4.f32 [%0], {%1, %2, %3, %4};"
                 :: "l"(op + 4), "f"(m[4]), "f"(m[5]), "f"(m[6]), "f"(m[7])
                 : "memory");
}

// ---------------------------------------------------------------------------
// Launch. Order chosen so overall launch #3 (0-based, incl. the harness's
// correctness call) = proj_mma_kernel -> ncu finally captures its profile.
// ---------------------------------------------------------------------------
extern "C" void kernel_launch(void* const* d_in, const int* in_sizes, int n_in,
                              void* d_out, int out_size) {
    const float* feat      = (const float*)d_in[0];   // [N, 64]
    const float* pseudo    = (const float*)d_in[1];   // [E, 3]
    const int*   src       = (const int*)  d_in[2];   // [E]
    const int*   dst       = (const int*)  d_in[3];   // [E]
    const float* W_fc      = (const float*)d_in[4];   // [256, 64]
    const float* mu        = (const float*)d_in[5];   // [4, 3]
    const float* inv_sigma = (const float*)d_in[6];   // [4, 3]
    const float* bias      = (const float*)d_in[7];   // [64]
    float* out = (float*)d_out;                       // [N, 64]

    // 0) W -> fp16
    wconv_kernel<<<(KH * IN_FEATS / 2 + 255) / 256, 256>>>(W_fc);

    // diagnostic shims (launches #1, #2)
    nop_kernel<<<1, 32>>>();
    nop_kernel<<<1, 32>>>();

    // 1) tensor-core projection + out = feat + bias   (launch #3 -> profiled)
    proj_mma_kernel<<<(N_NODES + NT - 1) / NT, 256>>>(feat, bias, out);

    // 2) edge scatter with vector atomics
    {
        long long threads = (long long)N_EDGES * 8;
        int blocks = (int)((threads + 255) / 256);            // 50000
        edge_kernel<<<blocks, 256>>>(pseudo, src, dst, mu, inv_sigma, out);
    }
}

// round 11
// speedup vs baseline: 1.3284x; 1.1768x over previous
#include <cuda_runtime.h>
#include <cuda_fp16.h>
#include <cuda_bf16.h>
#include <cstdint>

#define N_NODES   100000
#define N_EDGES   1600000
#define IN_FEATS  64
#define OUT_FEATS 64
#define DIM       3
#define N_KERNELS 4
#define KH        (N_KERNELS * OUT_FEATS)   // 256

// ---- scratch (allocation-free rule) ----
__device__ __half g_h[(size_t)N_NODES * KH];   // node projections fp16 (51 MB)
__device__ __half g_W16[KH * IN_FEATS];        // W_fc in fp16 (32 KB, L1-resident)

// ---------------------------------------------------------------------------
// Kernel 0: convert W_fc to fp16
// ---------------------------------------------------------------------------
__global__ void wconv_kernel(const float* __restrict__ W_fc) {
    int i = blockIdx.x * blockDim.x + threadIdx.x;       // half2 index
    if (i < KH * IN_FEATS / 2) {
        float2 v = reinterpret_cast<const float2*>(W_fc)[i];
        reinterpret_cast<__half2*>(g_W16)[i] = __floats2half2_rn(v.x, v.y);
    }
}

// Shims: keep ncu's captured launch (#3 overall) on proj_mma_kernel.
__global__ void nop_kernel() {}

// ---------------------------------------------------------------------------
// Kernel 1: PTX-mma projection + fused out = feat + bias.  (v4)
// mma.sync.aligned.m16n8k16.row.col.f32.f16.f16.f32, documented layouts:
//   A (4 regs): a0=(g,2t..2t+1) a1=(g+8,2t..) a2=(g,2t+8..) a3=(g+8,2t+8..)
//   B (2 regs): b0=(k=2t..2t+1, n=g) b1=(k=2t+8.., n=g)
//   C (4 regs): c0=(g,2t) c1=(g,2t+1) c2=(g+8,2t) c3=(g+8,2t+1)
// Block: 256 thr / 8 warps, NT=128 nodes. Warp w owns out-channels [32w,32w+32)
// (4 n-tiles), loops 8 m-tiles. B held in regs; accumulators convert to fp16
// in regs and store straight to g_h (lane-quad = 16B contiguous). No staging.
// ---------------------------------------------------------------------------
#define NT    128
#define AS_LD 72    // padded halves per As row -> conflict-free (4g+t)%32 LDS

__global__ __launch_bounds__(256) void proj_mma_kernel(const float* __restrict__ feat,
                                                       const float* __restrict__ bias,
                                                       float* __restrict__ out) {
    __shared__ __half As[NT * AS_LD];        // 18 KB

    const int tid  = threadIdx.x;
    const int warp = tid >> 5;
    const int lane = tid & 31;
    const int g    = lane >> 2;              // group id (row within tile)
    const int t    = lane & 3;               // thread-in-group
    const int node0 = blockIdx.x * NT;

    // --- load feat tile (fp32), convert to fp16 smem, fused out = feat + bias ---
    const float4* fsrc = reinterpret_cast<const float4*>(feat + (size_t)node0 * IN_FEATS);
    float4*       odst = reinterpret_cast<float4*>(out + (size_t)node0 * IN_FEATS);
    const float4* bp   = reinterpret_cast<const float4*>(bias);
    const int lim4 = (min(NT, N_NODES - node0)) * (IN_FEATS / 4);
#pragma unroll
    for (int q = 0; q < 8; q++) {
        int i = tid + q * 256;               // float4 index in tile (0..2047)
        float4 v = (i < lim4) ? fsrc[i] : make_float4(0.f, 0.f, 0.f, 0.f);
        int n = i >> 4;                       // node within tile
        int c = (i & 15) * 4;                 // channel
        __half2* adst = reinterpret_cast<__half2*>(As + n * AS_LD + c);
        adst[0] = __floats2half2_rn(v.x, v.y);
        adst[1] = __floats2half2_rn(v.z, v.w);
        if (i < lim4) {
            float4 b = __ldg(bp + (i & 15));
            v.x += b.x; v.y += b.y; v.z += b.z; v.w += b.w;
            odst[i] = v;                     // out = feat + bias
        }
    }
    __syncthreads();

    // --- B registers: 4 n-tiles x 4 k-steps x 2 regs, from L1-resident W ---
    const int n0w = warp * 32;
    uint32_t B[4][4][2];
#pragma unroll
    for (int nt = 0; nt < 4; nt++) {
        const int o = n0w + nt * 8 + g;                      // out channel (B col n=g)
        const uint32_t* wrow = reinterpret_cast<const uint32_t*>(g_W16 + o * IN_FEATS);
#pragma unroll
        for (int k = 0; k < 4; k++) {
            B[nt][k][0] = __ldg(wrow + k * 8 + t);           // k0+2t, k0+2t+1
            B[nt][k][1] = __ldg(wrow + k * 8 + t + 4);       // k0+2t+8, +9
        }
    }

    const uint32_t* As32 = reinterpret_cast<const uint32_t*>(As);

    // --- m-tile loop: A frags from smem (conflict-free), mma, reg-convert, store ---
#pragma unroll
    for (int mi = 0; mi < 8; mi++) {
        const int r0 = mi * 16 + g;
        uint32_t A[4][4];
#pragma unroll
        for (int k = 0; k < 4; k++) {
            A[k][0] = As32[(size_t)r0       * (AS_LD/2) + k * 8 + t];
            A[k][1] = As32[(size_t)(r0 + 8) * (AS_LD/2) + k * 8 + t];
            A[k][2] = As32[(size_t)r0       * (AS_LD/2) + k * 8 + t + 4];
            A[k][3] = As32[(size_t)(r0 + 8) * (AS_LD/2) + k * 8 + t + 4];
        }

        const int nodeA = node0 + mi * 16 + g;
        const int nodeB = nodeA + 8;
#pragma unroll
        for (int nt = 0; nt < 4; nt++) {
            float c0 = 0.f, c1 = 0.f, c2 = 0.f, c3 = 0.f;
#pragma unroll
            for (int k = 0; k < 4; k++) {
                asm volatile(
                    "mma.sync.aligned.m16n8k16.row.col.f32.f16.f16.f32 "
                    "{%0,%1,%2,%3}, {%4,%5,%6,%7}, {%8,%9}, {%0,%1,%2,%3};"
                    : "+f"(c0), "+f"(c1), "+f"(c2), "+f"(c3)
                    : "r"(A[k][0]), "r"(A[k][1]), "r"(A[k][2]), "r"(A[k][3]),
                      "r"(B[nt][k][0]), "r"(B[nt][k][1]));
            }
            const int col = n0w + nt * 8 + 2 * t;
            if (nodeA < N_NODES)
                *reinterpret_cast<__half2*>(g_h + (size_t)nodeA * KH + col) =
                    __floats2half2_rn(c0, c1);
            if (nodeB < N_NODES)
                *reinterpret_cast<__half2*>(g_h + (size_t)nodeB * KH + col) =
                    __floats2half2_rn(c2, c3);
        }
    }
}

// ---------------------------------------------------------------------------
// L2 residency via createpolicy + cache_hint.
// ---------------------------------------------------------------------------
__device__ __forceinline__ uint64_t make_policy_evict_last() {
    uint64_t p;
    asm("createpolicy.fractional.L2::evict_last.b64 %0, 1.0;" : "=l"(p));
    return p;
}
__device__ __forceinline__ uint64_t make_policy_evict_first() {
    uint64_t p;
    asm("createpolicy.fractional.L2::evict_first.b64 %0, 1.0;" : "=l"(p));
    return p;
}
__device__ __forceinline__ float4 ldg_hint_v4(const float4* p, uint64_t pol) {
    float4 v;
    asm volatile("ld.global.nc.L2::cache_hint.v4.f32 {%0, %1, %2, %3}, [%4], %5;"
                 : "=f"(v.x), "=f"(v.y), "=f"(v.z), "=f"(v.w) : "l"(p), "l"(pol));
    return v;
}
__device__ __forceinline__ float ldg_hint_f32(const float* p, uint64_t pol) {
    float v;
    asm volatile("ld.global.nc.L2::cache_hint.f32 %0, [%1], %2;"
                 : "=f"(v) : "l"(p), "l"(pol));
    return v;
}
__device__ __forceinline__ int ldg_hint_s32(const int* p, uint64_t pol) {
    int v;
    asm volatile("ld.global.nc.L2::cache_hint.b32 %0, [%1], %2;"
                 : "=r"(v) : "l"(p), "l"(pol));
    return v;
}

// ---------------------------------------------------------------------------
// Kernel 2: edge scatter (unchanged: ~132 us).
// ---------------------------------------------------------------------------
__global__ __launch_bounds__(256) void edge_kernel(const float* __restrict__ pseudo,
                                                   const int*   __restrict__ src,
                                                   const int*   __restrict__ dst,
                                                   const float* __restrict__ mu,
                                                   const float* __restrict__ inv_sigma,
                                                   float* __restrict__ out) {
    const int gid = blockIdx.x * blockDim.x + threadIdx.x;
    const int e   = gid >> 3;                  // edge index
    if (e >= N_EDGES) return;

    const uint64_t pol_keep   = make_policy_evict_last();
    const uint64_t pol_stream = make_policy_evict_first();

    const int lane = threadIdx.x & 31;
    const int sub  = gid & 7;
    const int kid  = sub & 3;

    float px = ldg_hint_f32(pseudo + 3*e + 0, pol_stream);
    float py = ldg_hint_f32(pseudo + 3*e + 1, pol_stream);
    float pz = ldg_hint_f32(pseudo + 3*e + 2, pol_stream);

    float d0 = px - __ldg(mu + kid*3 + 0);
    float d1 = py - __ldg(mu + kid*3 + 1);
    float d2 = pz - __ldg(mu + kid*3 + 2);
    float s0 = __ldg(inv_sigma + kid*3 + 0);
    float s1 = __ldg(inv_sigma + kid*3 + 1);
    float s2 = __ldg(inv_sigma + kid*3 + 2);

    float acc = d0*d0*s0*s0 + d1*d1*s1*s1 + d2*d2*s2*s2;
    float gv  = __expf(-0.5f * acc);

    const unsigned FULL = 0xffffffffu;
    const int base = lane & 24;
    float g0 = __shfl_sync(FULL, gv, base + 0);
    float g1 = __shfl_sync(FULL, gv, base + 1);
    float g2 = __shfl_sync(FULL, gv, base + 2);
    float g3 = __shfl_sync(FULL, gv, base + 3);

    const int s = ldg_hint_s32(src + e, pol_stream);
    const int d = ldg_hint_s32(dst + e, pol_stream);

    const float4* hp = reinterpret_cast<const float4*>(g_h + (size_t)s * KH);
    float4 r0 = ldg_hint_v4(hp + 0*8 + sub, pol_keep);
    float4 r1 = ldg_hint_v4(hp + 1*8 + sub, pol_keep);
    float4 r2 = ldg_hint_v4(hp + 2*8 + sub, pol_keep);
    float4 r3 = ldg_hint_v4(hp + 3*8 + sub, pol_keep);

    const __half2* h0 = reinterpret_cast<const __half2*>(&r0);
    const __half2* h1 = reinterpret_cast<const __half2*>(&r1);
    const __half2* h2 = reinterpret_cast<const __half2*>(&r2);
    const __half2* h3 = reinterpret_cast<const __half2*>(&r3);

    float m[8];
#pragma unroll
    for (int q = 0; q < 4; q++) {
        float2 a = __half22float2(h0[q]);
        float2 b = __half22float2(h1[q]);
        float2 c = __half22float2(h2[q]);
        float2 dd = __half22float2(h3[q]);
        m[2*q+0] = g0*a.x + g1*b.x + g2*c.x + g3*dd.x;
        m[2*q+1] = g0*a.y + g1*b.y + g2*c.y + g3*dd.y;
    }

    float* op = out + (size_t)d * OUT_FEATS + sub * 8;
    asm volatile("red.global.add.v4.f32 [%0], {%1, %2, %3, %4};"
                 :: "l"(op), "f"(m[0]), "f"(m[1]), "f"(m[2]), "f"(m[3])
                 : "memory");
    asm volatile("red.global.add.v4.f32 [%0], {%1, %2, %3, %4};"
                 :: "l"(op + 4), "f"(m[4]), "f"(m[5]), "f"(m[6]), "f"(m[7])
                 : "memory");
}

// ---------------------------------------------------------------------------
// Launch. Overall launch #3 (incl. harness correctness call) = proj_mma.
// ---------------------------------------------------------------------------
extern "C" void kernel_launch(void* const* d_in, const int* in_sizes, int n_in,
                              void* d_out, int out_size) {
    const float* feat      = (const float*)d_in[0];   // [N, 64]
    const float* pseudo    = (const float*)d_in[1];   // [E, 3]
    const int*   src       = (const int*)  d_in[2];   // [E]
    const int*   dst       = (const int*)  d_in[3];   // [E]
    const float* W_fc      = (const float*)d_in[4];   // [256, 64]
    const float* mu        = (const float*)d_in[5];   // [4, 3]
    const float* inv_sigma = (const float*)d_in[6];   // [4, 3]
    const float* bias      = (const float*)d_in[7];   // [64]
    float* out = (float*)d_out;                       // [N, 64]

    // 0) W -> fp16
    wconv_kernel<<<(KH * IN_FEATS / 2 + 255) / 256, 256>>>(W_fc);

    // shims (launches #1, #2)
    nop_kernel<<<1, 32>>>();
    nop_kernel<<<1, 32>>>();

    // 1) PTX-mma projection + out = feat + bias   (launch #3 -> profiled)
    proj_mma_kernel<<<(N_NODES + NT - 1) / NT, 256>>>(feat, bias, out);

    // 2) edge scatter with vector atomics
    {
        long long threads = (long long)N_EDGES * 8;
        int blocks = (int)((threads + 255) / 256);            // 50000
        edge_kernel<<<blocks, 256>>>(pseudo, src, dst, mu, inv_sigma, out);
    }
}